// round 1
// baseline (speedup 1.0000x reference)
#include <cuda_runtime.h>

#define BATCH 16
#define CDIM 256
#define HWDIM 2304
#define PB (CDIM * HWDIM)            // 589824 floats per batch

// Scratch (device globals — allocation-free per harness rules)
__device__ float g_inv[BATCH];
__device__ float g_S[(size_t)BATCH * HWDIM * HWDIM];   // 339.7 MB: relu(G*inv)^2
__device__ float g_T[(size_t)BATCH * PB];              // 37.7 MB : 1x1-conv result

// ---------------------------------------------------------------------------
// Kernel 1: per-batch inverse squared L2 norm
// ---------------------------------------------------------------------------
__global__ void sumsq_kernel(const float* __restrict__ x) {
    const int b = blockIdx.x;
    const float4* p = (const float4*)(x + (size_t)b * PB);
    const int n4 = PB / 4;  // 147456
    float s = 0.f;
    for (int i = threadIdx.x; i < n4; i += blockDim.x) {
        float4 v = p[i];
        s += v.x * v.x + v.y * v.y + v.z * v.z + v.w * v.w;
    }
    __shared__ float red[512];
    red[threadIdx.x] = s;
    __syncthreads();
    for (int off = blockDim.x >> 1; off > 0; off >>= 1) {
        if (threadIdx.x < (unsigned)off) red[threadIdx.x] += red[threadIdx.x + off];
        __syncthreads();
    }
    if (threadIdx.x == 0) g_inv[b] = 1.0f / red[0];
}

// ---------------------------------------------------------------------------
// Generic 128x128x8 SGEMM, 256 threads, 8x8 microtiles (strided 4+4 fragments)
//   C[M,N] = A(row-major, lda) @ B(row-major, ldb)   all dims multiples of tile
// EPI 0: C = relu(acc * g_inv[bz])^2            (GEMM1 -> g_S)
// EPI 1: C = acc + bias[row]                    (GEMM2 -> g_T)
// EPI 2: C = acc                                (GEMM3 -> d_out; A=g_S, B=g_T)
// ---------------------------------------------------------------------------
template <int EPI>
__global__ void __launch_bounds__(256, 2)
sgemm128(const float* __restrict__ Ag, int lda, size_t sA,
         const float* __restrict__ Bg, int ldb, size_t sB,
         float* __restrict__ Cg, int ldc, size_t sC,
         int K, const float* __restrict__ bias)
{
    const int bz = blockIdx.z;
    const float* A;
    const float* Bp;
    float* Cp;
    if (EPI == 2) {        // GEMM3: Y = S @ Tview
        A  = g_S + (size_t)bz * sA;
        Bp = g_T + (size_t)bz * sB;
        Cp = Cg  + (size_t)bz * sC;
    } else if (EPI == 0) { // GEMM1: G = M1 @ M2 (both views of x)
        A  = Ag + (size_t)bz * sA;
        Bp = Bg + (size_t)bz * sB;
        Cp = g_S + (size_t)bz * sC;
    } else {               // GEMM2: T = W @ X
        A  = Ag;                       // W, shared across batches
        Bp = Bg + (size_t)bz * sB;
        Cp = g_T + (size_t)bz * sC;
    }

    const int m0 = blockIdx.y * 128;
    const int n0 = blockIdx.x * 128;

    __shared__ float As[8][132];   // padded to reduce transpose-store conflicts
    __shared__ float Bs[8][128];

    const int tid = threadIdx.x;
    const int tx = tid & 15;       // 0..15  -> col groups {tx*4, 64+tx*4}
    const int ty = tid >> 4;       // 0..15  -> row groups {ty*4, 64+ty*4}

    float acc[8][8];
#pragma unroll
    for (int i = 0; i < 8; i++)
#pragma unroll
        for (int j = 0; j < 8; j++) acc[i][j] = 0.f;

    // global-load assignments
    const int arow = tid >> 1;         // 0..127
    const int akq  = (tid & 1) * 4;    // 0 or 4
    const int bk   = tid >> 5;         // 0..7
    const int bn   = (tid & 31) * 4;   // 0..124

    const float* aptr = A  + (size_t)(m0 + arow) * lda + akq;
    const float* bptr = Bp + (size_t)bk * ldb + n0 + bn;

    // prefetch first tiles
    float4 av = *(const float4*)(aptr);
    float4 bv = *(const float4*)(bptr);

    for (int k0 = 0; k0 < K; k0 += 8) {
        __syncthreads();   // previous iteration's reads are done
        As[akq + 0][arow] = av.x;
        As[akq + 1][arow] = av.y;
        As[akq + 2][arow] = av.z;
        As[akq + 3][arow] = av.w;
        *(float4*)&Bs[bk][bn] = bv;
        __syncthreads();

        // prefetch next tiles (overlaps with compute below)
        if (k0 + 8 < K) {
            av = *(const float4*)(aptr + (k0 + 8));
            bv = *(const float4*)(bptr + (size_t)(k0 + 8) * ldb);
        }

#pragma unroll
        for (int k = 0; k < 8; k++) {
            float a[8], b[8];
            *(float4*)&a[0] = *(const float4*)&As[k][ty * 4];
            *(float4*)&a[4] = *(const float4*)&As[k][64 + ty * 4];
            *(float4*)&b[0] = *(const float4*)&Bs[k][tx * 4];
            *(float4*)&b[4] = *(const float4*)&Bs[k][64 + tx * 4];
#pragma unroll
            for (int i = 0; i < 8; i++)
#pragma unroll
                for (int j = 0; j < 8; j++) acc[i][j] = fmaf(a[i], b[j], acc[i][j]);
        }
    }

    // epilogue
    float inv = 0.f;
    if (EPI == 0) inv = g_inv[bz];

#pragma unroll
    for (int ri = 0; ri < 2; ri++) {
#pragma unroll
        for (int i = 0; i < 4; i++) {
            const int gr = m0 + ri * 64 + ty * 4 + i;
            float brow = 0.f;
            if (EPI == 1) brow = bias[gr];
#pragma unroll
            for (int ci = 0; ci < 2; ci++) {
                float4 v;
                v.x = acc[ri * 4 + i][ci * 4 + 0];
                v.y = acc[ri * 4 + i][ci * 4 + 1];
                v.z = acc[ri * 4 + i][ci * 4 + 2];
                v.w = acc[ri * 4 + i][ci * 4 + 3];
                if (EPI == 0) {
                    float r;
                    r = fmaxf(v.x * inv, 0.f); v.x = r * r;
                    r = fmaxf(v.y * inv, 0.f); v.y = r * r;
                    r = fmaxf(v.z * inv, 0.f); v.z = r * r;
                    r = fmaxf(v.w * inv, 0.f); v.w = r * r;
                } else if (EPI == 1) {
                    v.x += brow; v.y += brow; v.z += brow; v.w += brow;
                }
                *(float4*)&Cp[(size_t)gr * ldc + n0 + ci * 64 + tx * 4] = v;
            }
        }
    }
}

// ---------------------------------------------------------------------------
// Launch
//   d_in[0] = x    (16,256,48,48) f32
//   d_in[1] = W    (256,256)      f32
//   d_in[2] = bias (256,)         f32
//   d_out   = y    (16,256,48,48) f32
// ---------------------------------------------------------------------------
extern "C" void kernel_launch(void* const* d_in, const int* in_sizes, int n_in,
                              void* d_out, int out_size)
{
    const float* x    = (const float*)d_in[0];
    const float* W    = (const float*)d_in[1];
    const float* bias = (const float*)d_in[2];
    float* out        = (float*)d_out;

    // 1) per-batch 1/||x||^2
    sumsq_kernel<<<BATCH, 512>>>(x);

    // 2) GEMM2: T[o,p] = W @ X + bias   (independent of step 1)
    {
        dim3 grid(HWDIM / 128, CDIM / 128, BATCH);
        sgemm128<1><<<grid, 256>>>(W, CDIM, 0,
                                   x, HWDIM, (size_t)PB,
                                   nullptr, HWDIM, (size_t)PB,
                                   CDIM, bias);
    }

    // 3) GEMM1: S[n,m] = relu( (M1 @ M2) * inv )^2
    {
        dim3 grid(HWDIM / 128, HWDIM / 128, BATCH);
        sgemm128<0><<<grid, 256>>>(x, CDIM, (size_t)PB,
                                   x, HWDIM, (size_t)PB,
                                   nullptr, HWDIM, (size_t)HWDIM * HWDIM,
                                   CDIM, nullptr);
    }

    // 4) GEMM3: Y[n,j] = S @ Tview  -> d_out directly
    {
        dim3 grid(CDIM / 128, HWDIM / 128, BATCH);
        sgemm128<2><<<grid, 256>>>(nullptr, HWDIM, (size_t)HWDIM * HWDIM,
                                   nullptr, CDIM, (size_t)PB,
                                   out, CDIM, (size_t)PB,
                                   HWDIM, nullptr);
    }
}